// round 16
// baseline (speedup 1.0000x reference)
#include <cuda_runtime.h>
#include <cuda_fp16.h>
#include <cstddef>
#include <cstdint>

#define D_MODEL   1024
#define NUM_HEADS 16
#define DEPTH     64
#define BATCH     2
#define SEQ       2048
#define M_ROWS    (BATCH * SEQ)   // 4096

// Q-path scale: (1/sqrt(64)) * log2(e)  — folds softmax scaling + exp->ex2
#define QSCALE 0.18033688011112042f

// ---------------------------------------------------------------------------
// Scratch (all fp16 intermediates; f32 only for biases & final output)
// ---------------------------------------------------------------------------
__device__ __half g_qf[M_ROWS * D_MODEL];    // converted inputs
__device__ __half g_kf[M_ROWS * D_MODEL];
__device__ __half g_vf[M_ROWS * D_MODEL];
__device__ __half g_wq[D_MODEL * D_MODEL];   // converted weights (wq pre-scaled)
__device__ __half g_wk[D_MODEL * D_MODEL];
__device__ __half g_wv[D_MODEL * D_MODEL];
__device__ __half g_wd[D_MODEL * D_MODEL];
__device__ __half g_qh[BATCH * NUM_HEADS * SEQ * DEPTH];   // projections [B,H,S,64]
__device__ __half g_kh[BATCH * NUM_HEADS * SEQ * DEPTH];
__device__ __half g_vh[BATCH * NUM_HEADS * SEQ * DEPTH];
__device__ __half g_att[M_ROWS * D_MODEL];   // attention out, concat layout

// ---------------------------------------------------------------------------
// Helpers
// ---------------------------------------------------------------------------
__device__ __forceinline__ uint32_t smem_u32(const void* p) {
    uint32_t a;
    asm("{ .reg .u64 t; cvta.to.shared.u64 t, %1; cvt.u32.u64 %0, t; }" : "=r"(a) : "l"(p));
    return a;
}

__device__ __forceinline__ unsigned pack2(float a, float b) {
    __half2 h = __floats2half2_rn(a, b);   // low half = a
    return *reinterpret_cast<unsigned*>(&h);
}

__device__ __forceinline__ float ex2f(float x) {
    float y;
    asm("ex2.approx.f32 %0, %1;" : "=f"(y) : "f"(x));
    return y;
}

// paired exponential: ex2 on both halves of a packed half2
__device__ __forceinline__ unsigned h2ex2(unsigned x) {
    unsigned y;
    asm("ex2.approx.f16x2 %0, %1;" : "=r"(y) : "r"(x));
    return y;
}

__device__ __forceinline__ void mma16(float* c, const unsigned* a, const unsigned* b) {
    asm volatile(
        "mma.sync.aligned.m16n8k16.row.col.f32.f16.f16.f32 "
        "{%0,%1,%2,%3},{%4,%5,%6,%7},{%8,%9},{%0,%1,%2,%3};"
        : "+f"(c[0]), "+f"(c[1]), "+f"(c[2]), "+f"(c[3])
        : "r"(a[0]), "r"(a[1]), "r"(a[2]), "r"(a[3]), "r"(b[0]), "r"(b[1]));
}

__device__ __forceinline__ void ldm_x4(unsigned* d, uint32_t addr) {
    asm volatile("ldmatrix.sync.aligned.m8n8.x4.shared.b16 {%0,%1,%2,%3}, [%4];"
                 : "=r"(d[0]), "=r"(d[1]), "=r"(d[2]), "=r"(d[3]) : "r"(addr));
}
__device__ __forceinline__ void ldm_x4_t(unsigned* d, uint32_t addr) {
    asm volatile("ldmatrix.sync.aligned.m8n8.x4.trans.shared.b16 {%0,%1,%2,%3}, [%4];"
                 : "=r"(d[0]), "=r"(d[1]), "=r"(d[2]), "=r"(d[3]) : "r"(addr));
}

#define CP16(dst, src) \
    asm volatile("cp.async.cg.shared.global [%0], [%1], 16;" :: "r"(dst), "l"(src) : "memory")
#define CP_COMMIT() asm volatile("cp.async.commit_group;" ::: "memory")
#define CP_WAIT(n)  asm volatile("cp.async.wait_group %0;" :: "n"(n) : "memory")

// ---------------------------------------------------------------------------
// Conversion kernel (f32 -> f16): z 0..2 inputs (q,k,v), 3..6 weights.
// wq (z==3) pre-scaled by QSCALE.
// ---------------------------------------------------------------------------
__global__ void cvt_all(const float* __restrict__ q, const float* __restrict__ k,
                        const float* __restrict__ v,
                        const float* __restrict__ w0, const float* __restrict__ w1,
                        const float* __restrict__ w2, const float* __restrict__ w3,
                        __half* dq, __half* dk, __half* dv,
                        __half* d0, __half* d1, __half* d2, __half* d3)
{
    const int z = blockIdx.z;
    const int n = (z < 3) ? (M_ROWS * D_MODEL / 4) : (D_MODEL * D_MODEL / 4);
    const int i = blockIdx.x * blockDim.x + threadIdx.x;
    if (i >= n) return;
    const float* s;
    __half* d;
    float sc = 1.0f;
    switch (z) {
        case 0: s = q;  d = dq; break;
        case 1: s = k;  d = dk; break;
        case 2: s = v;  d = dv; break;
        case 3: s = w0; d = d0; sc = QSCALE; break;
        case 4: s = w1; d = d1; break;
        case 5: s = w2; d = d2; break;
        default: s = w3; d = d3; break;
    }
    const float4 f = ((const float4*)s)[i];
    uint2 u;
    u.x = pack2(f.x * sc, f.y * sc);
    u.y = pack2(f.z * sc, f.w * sc);
    ((uint2*)d)[i] = u;
}

// ---------------------------------------------------------------------------
// fp16 GEMM: C = A(M,K) @ W^T(N,K) + bias*bscale.  Block 128x128, BK=64,
// 256 thr, 8 warps (2m x 4n), warp tile 64x32, 3-stage cp.async pipeline
// (dynamic smem 96KB). No empty commit groups: steady state commits one real
// group per iter (wait_group 1); tail iterations use wait_group 0.
// Smem per stage: A 128 rows x 128B + B 128 rows x 128B, swizzle
//   GK(r,c) = r*128 + ((c ^ (r&7)) * 16),  c = 16B chunk 0..7.
// ---------------------------------------------------------------------------
#define GK(r, c) ((r) * 128 + (((c) ^ ((r) & 7)) << 4))
#define GEMM_NSTEPS 16   // 1024 / 64
#define GEMM_NSTAGE 3
#define GEMM_STAGE_BYTES 32768
#define GEMM_SMEM_BYTES (GEMM_NSTAGE * GEMM_STAGE_BYTES)   // 98304

__device__ __forceinline__ void gemm_h_core(
    const __half* __restrict__ A, const __half* __restrict__ W,
    const float* __restrict__ bias, void* __restrict__ Cout,
    int head_split, int m0, int n0, float bscale)
{
    extern __shared__ __align__(16) char gsm[];
    const uint32_t sb = smem_u32(gsm);

    const int tid  = threadIdx.x;
    const int lane = tid & 31;
    const int w    = tid >> 5;
    const int wm   = w >> 2;           // 0..1
    const int wn   = w & 3;            // 0..3

    float acc[4][4][4];
#pragma unroll
    for (int i = 0; i < 4; i++)
#pragma unroll
        for (int j = 0; j < 4; j++)
#pragma unroll
            for (int e = 0; e < 4; e++) acc[i][j][e] = 0.f;

    // staging: t<128 -> A row t; t>=128 -> B row t-128; 8 x 16B chunks (128B/row)
    const int srow = tid & 127;
    const __half* gsrc = (tid < 128) ? (A + (size_t)(m0 + srow) * D_MODEL)
                                     : (W + (size_t)(n0 + srow) * D_MODEL);
    const uint32_t sbase0 = sb + ((tid < 128) ? 0 : 16384);
    uint32_t sdst[8];
#pragma unroll
    for (int c = 0; c < 8; c++) sdst[c] = sbase0 + GK(srow, c);

    // prologue: stages 0,1 (2 groups in flight)
#pragma unroll
    for (int st = 0; st < 2; st++) {
#pragma unroll
        for (int c = 0; c < 8; c++)
            CP16(sdst[c] + st * GEMM_STAGE_BYTES, gsrc + st * 64 + c * 8);
        CP_COMMIT();
    }

    // fragment row bases (addresses computed inline per kt: ALU is idle)
    int pA[4], mAa[4];
#pragma unroll
    for (int i = 0; i < 4; i++) {
        const int r = wm * 64 + i * 16 + (lane & 7) + ((lane >> 3) & 1) * 8;
        pA[i] = r * 128; mAa[i] = r & 7;
    }
    int pB[2], mBb[2];
#pragma unroll
    for (int jp = 0; jp < 2; jp++) {
        const int r = wn * 32 + (2 * jp + ((lane >> 4) & 1)) * 8 + (lane & 7);
        pB[jp] = r * 128; mBb[jp] = r & 7;
    }
    const int cA = lane >> 4;          // A chunk parity bit
    const int cB = (lane >> 3) & 1;    // B chunk parity bit

#pragma unroll 1
    for (int s = 0; s < GEMM_NSTEPS; s++) {
        if (s + 2 < GEMM_NSTEPS) {
            CP_WAIT(1);        // newest outstanding = stage s+1's group; stage s resident
            __syncthreads();
            const int st = (s + 2) % GEMM_NSTAGE;
#pragma unroll
            for (int c = 0; c < 8; c++)
                CP16(sdst[c] + st * GEMM_STAGE_BYTES, gsrc + (s + 2) * 64 + c * 8);
            CP_COMMIT();
        } else {
            CP_WAIT(0);        // tail: everything resident
            __syncthreads();
        }

        const uint32_t ab = sb + (s % GEMM_NSTAGE) * GEMM_STAGE_BYTES;
        const uint32_t bb = ab + 16384;
#pragma unroll
        for (int kt = 0; kt < 4; kt++) {
            unsigned bf[4][2];
#pragma unroll
            for (int jp = 0; jp < 2; jp++) {
                unsigned t4[4];
                ldm_x4(t4, bb + pB[jp] + (((2 * kt + cB) ^ mBb[jp]) << 4));
                bf[2 * jp][0]     = t4[0]; bf[2 * jp][1]     = t4[1];
                bf[2 * jp + 1][0] = t4[2]; bf[2 * jp + 1][1] = t4[3];
            }
#pragma unroll
            for (int i = 0; i < 4; i++) {
                unsigned af[4];
                ldm_x4(af, ab + pA[i] + (((2 * kt + cA) ^ mAa[i]) << 4));
#pragma unroll
                for (int j = 0; j < 4; j++) mma16(acc[i][j], af, bf[j]);
            }
        }
    }

    // ---- epilogue ----
#pragma unroll
    for (int i = 0; i < 4; i++) {
#pragma unroll
        for (int j = 0; j < 4; j++) {
            const int m = m0 + wm * 64 + i * 16 + (lane >> 2);
            const int n = n0 + wn * 32 + j * 8 + 2 * (lane & 3);
            const float2 bb2 = *(const float2*)(bias + n);
            const float bx = bb2.x * bscale, by = bb2.y * bscale;
            const float v00 = acc[i][j][0] + bx, v01 = acc[i][j][1] + by;
            const float v10 = acc[i][j][2] + bx, v11 = acc[i][j][3] + by;
            if (head_split) {
                __half* C = (__half*)Cout;
                const int hh = n >> 6, d = n & 63;
                const int b0r = m >> 11, s0r = m & (SEQ - 1);
                const int b1r = (m + 8) >> 11, s1r = (m + 8) & (SEQ - 1);
                *(unsigned*)&C[(((size_t)b0r * NUM_HEADS + hh) * SEQ + s0r) * DEPTH + d] = pack2(v00, v01);
                *(unsigned*)&C[(((size_t)b1r * NUM_HEADS + hh) * SEQ + s1r) * DEPTH + d] = pack2(v10, v11);
            } else {
                float* C = (float*)Cout;
                float2 o0; o0.x = v00; o0.y = v01;
                float2 o1; o1.x = v10; o1.y = v11;
                *(float2*)&C[(size_t)m * D_MODEL + n] = o0;
                *(float2*)&C[(size_t)(m + 8) * D_MODEL + n] = o1;
            }
        }
    }
}

__global__ __launch_bounds__(256, 2) void gemm_qkv(
    const __half* __restrict__ qf, const __half* __restrict__ kf, const __half* __restrict__ vf,
    const __half* __restrict__ wq, const float* __restrict__ bq,
    const __half* __restrict__ wk, const float* __restrict__ bk,
    const __half* __restrict__ wv, const float* __restrict__ bv,
    __half* __restrict__ qh, __half* __restrict__ kh, __half* __restrict__ vh)
{
    const int z = blockIdx.z;
    const __half* A = (z == 0) ? qf : (z == 1) ? kf : vf;
    const __half* W = (z == 0) ? wq : (z == 1) ? wk : wv;
    const float*  B = (z == 0) ? bq : (z == 1) ? bk : bv;
    __half*       C = (z == 0) ? qh : (z == 1) ? kh : vh;
    const float bs  = (z == 0) ? QSCALE : 1.0f;
    gemm_h_core(A, W, B, C, 1, blockIdx.y * 128, blockIdx.x * 128, bs);
}

__global__ __launch_bounds__(256, 2) void gemm_dense(
    const __half* __restrict__ A, const __half* __restrict__ W,
    const float* __restrict__ bias, float* __restrict__ C)
{
    gemm_h_core(A, W, bias, C, 0, blockIdx.y * 128, blockIdx.x * 128, 1.0f);
}

// ---------------------------------------------------------------------------
// fp16 FA2 causal attention, log2-domain softmax with PAIRED f16x2 ex2.
// 256 thr (8 warps), 128 q/block (16 rows/warp), 64-key tiles,
// paired q-tiles (bx, 15-bx), double-buffered cp.async K/V.
// ---------------------------------------------------------------------------
#define KOFF(r, c) ((r) * 128 + (((c) ^ ((r) & 7)) * 16))
#define ATTN_THREADS 256

__global__ __launch_bounds__(ATTN_THREADS, 2) void attn_h(
    const __half* __restrict__ Qg, const __half* __restrict__ Kg,
    const __half* __restrict__ Vg, __half* __restrict__ Og)
{
    __shared__ __align__(16) char asmm[2 * 16384];   // 2 bufs x (K 8KB + V 8KB)
    const uint32_t sb = smem_u32(asmm);

    const int tid  = threadIdx.x;
    const int lane = tid & 31;
    const int w    = tid >> 5;
    const int b    = blockIdx.z;
    const int h    = blockIdx.y;

    const size_t hoff = ((size_t)(b * NUM_HEADS + h) * SEQ) * DEPTH;
    const __half* kb = Kg + hoff;
    const __half* vb = Vg + hoff;

    const int r0 = lane >> 2;   // 0..7
    const int c0 = lane & 3;    // 0..3

    const int strow = (tid & 127) >> 1;
    const int stc0  = (tid & 1) * 4;
    const __half* stsrc = ((tid < 128) ? kb : vb) + (size_t)strow * DEPTH + stc0 * 8;
    uint32_t stdst[4];
#pragma unroll
    for (int i = 0; i < 4; i++)
        stdst[i] = sb + ((tid < 128) ? 0 : 8192) + KOFF(strow, stc0 + i);

    int rK[4];
#pragma unroll
    for (int jp = 0; jp < 4; jp++)
        rK[jp] = (2 * jp + ((lane >> 4) & 1)) * 8 + (lane & 7);
    const int hK  = (lane >> 3) & 1;
    const int rVl = (lane & 7) + ((lane >> 3) & 1) * 8;
    const int cVb = (lane >> 4) & 1;

#pragma unroll 1
    for (int pass = 0; pass < 2; pass++) {
        const int p  = pass ? (15 - (int)blockIdx.x) : (int)blockIdx.x;
        const int q0 = p * 128;

        unsigned qa[4][4];
        {
            const __half* qb = Qg + hoff + (size_t)(q0 + w * 16) * DEPTH;
#pragma unroll
            for (int kt = 0; kt < 4; kt++) {
                qa[kt][0] = *(const unsigned*)(qb + (size_t)(r0)     * DEPTH + kt * 16 + 2 * c0);
                qa[kt][1] = *(const unsigned*)(qb + (size_t)(r0 + 8) * DEPTH + kt * 16 + 2 * c0);
                qa[kt][2] = *(const unsigned*)(qb + (size_t)(r0)     * DEPTH + kt * 16 + 8 + 2 * c0);
                qa[kt][3] = *(const unsigned*)(qb + (size_t)(r0 + 8) * DEPTH + kt * 16 + 8 + 2 * c0);
            }
        }

        float o[8][4];
#pragma unroll
        for (int j = 0; j < 8; j++)
#pragma unroll
            for (int e = 0; e < 4; e++) o[j][e] = 0.f;
        float m0r = -1e30f, m1r = -1e30f;
        float l0r = 0.f,    l1r = 0.f;

        const int ntile = 2 * p + 2;
        const int qhiW  = q0 + w * 16 + 15;
        const int qrow  = q0 + w * 16 + r0;

#pragma unroll
        for (int i = 0; i < 4; i++) CP16(stdst[i], stsrc + i * 8);
        CP_COMMIT();

#pragma unroll 1
        for (int t = 0; t < ntile; t++) {
            CP_WAIT(0);
            __syncthreads();
            if (t + 1 < ntile) {
                const uint32_t bo = ((t + 1) & 1) * 16384;
                const __half* src = stsrc + (size_t)(t + 1) * 64 * DEPTH;
#pragma unroll
                for (int i = 0; i < 4; i++) CP16(stdst[i] + bo, src + i * 8);
                CP_COMMIT();
            }
            if (t * 64 > qhiW) continue;

            const uint32_t kbuf = sb + (t & 1) * 16384;
            const uint32_t vbuf = kbuf + 8192;

            // ---- S = Q @ K^T  (scores already in log2 domain) ----
            float s[8][4];
#pragma unroll
            for (int j = 0; j < 8; j++)
#pragma unroll
                for (int e = 0; e < 4; e++) s[j][e] = 0.f;
#pragma unroll
            for (int kt = 0; kt < 4; kt++) {
#pragma unroll
                for (int jp = 0; jp < 4; jp++) {
                    unsigned t4[4];
                    ldm_x4(t4, kbuf + rK[jp] * 128 + (((2 * kt + hK) ^ (rK[jp] & 7)) << 4));
                    unsigned bf0[2] = {t4[0], t4[1]};
                    unsigned bf1[2] = {t4[2], t4[3]};
                    mma16(s[2 * jp],     qa[kt], bf0);
                    mma16(s[2 * jp + 1], qa[kt], bf1);
                }
            }

            // ---- causal mask + online softmax (base-2, paired f16x2 exp) ----
            const bool diag = (t >= ntile - 2);
            float mx0 = -1e30f, mx1 = -1e30f;
#pragma unroll
            for (int j = 0; j < 8; j++) {
                if (diag) {
#pragma unroll
                    for (int e = 0; e < 4; e++) {
                        const int key = t * 64 + j * 8 + 2 * (lane & 3) + (e & 1);
                        const int qq  = qrow + ((e >> 1) << 3);
                        if (key > qq) s[j][e] = -1e30f;
                    }
                }
                mx0 = fmaxf(mx0, fmaxf(s[j][0], s[j][1]));
                mx1 = fmaxf(mx1, fmaxf(s[j][2], s[j][3]));
            }
            mx0 = fmaxf(mx0, __shfl_xor_sync(0xffffffffu, mx0, 1));
            mx0 = fmaxf(mx0, __shfl_xor_sync(0xffffffffu, mx0, 2));
            mx1 = fmaxf(mx1, __shfl_xor_sync(0xffffffffu, mx1, 1));
            mx1 = fmaxf(mx1, __shfl_xor_sync(0xffffffffu, mx1, 2));

            const float mn0 = fmaxf(m0r, mx0);
            const float mn1 = fmaxf(m1r, mx1);
            const float al0 = ex2f(m0r - mn0);
            const float al1 = ex2f(m1r - mn1);

            unsigned p01[8], p23[8];
            __half2 a01 = __floats2half2_rn(0.f, 0.f);
            __half2 a23 = a01;
#pragma unroll
            for (int j = 0; j < 8; j++) {
                p01[j] = h2ex2(pack2(s[j][0] - mn0, s[j][1] - mn0));
                p23[j] = h2ex2(pack2(s[j][2] - mn1, s[j][3] - mn1));
                a01 = __hadd2(a01, *reinterpret_cast<__half2*>(&p01[j]));
                a23 = __hadd2(a23, *reinterpret_cast<__half2*>(&p23[j]));
            }
            float ls0 = __low2float(a01) + __high2float(a01);
            float ls1 = __low2float(a23) + __high2float(a23);
            ls0 += __shfl_xor_sync(0xffffffffu, ls0, 1);
            ls0 += __shfl_xor_sync(0xffffffffu, ls0, 2);
            ls1 += __shfl_xor_sync(0xffffffffu, ls1, 1);
            ls1 += __shfl_xor_sync(0xffffffffu, ls1, 2);

            l0r = l0r * al0 + ls0;
            l1r = l1r * al1 + ls1;
            m0r = mn0; m1r = mn1;

#pragma unroll
            for (int j = 0; j < 8; j++) {
                o[j][0] *= al0; o[j][1] *= al0;
                o[j][2] *= al1; o[j][3] *= al1;
            }

            // ---- O += P @ V : A-frags are the h2ex2 outputs directly ----
#pragma unroll
            for (int kt = 0; kt < 4; kt++) {
                unsigned af[4];
                af[0] = p01[2 * kt];
                af[1] = p23[2 * kt];
                af[2] = p01[2 * kt + 1];
                af[3] = p23[2 * kt + 1];
                const int rV = kt * 16 + rVl;
#pragma unroll
                for (int jp = 0; jp < 4; jp++) {
                    unsigned t4[4];
                    ldm_x4_t(t4, vbuf + rV * 128 + (((2 * jp + cVb) ^ (rV & 7)) << 4));
                    unsigned bf0[2] = {t4[0], t4[1]};
                    unsigned bf1[2] = {t4[2], t4[3]};
                    mma16(o[2 * jp],     af, bf0);
                    mma16(o[2 * jp + 1], af, bf1);
                }
            }
        }

        // ---- epilogue ----
        const float inv0 = 1.f / l0r;
        const float inv1 = 1.f / l1r;
        const int qq = q0 + w * 16 + r0;
#pragma unroll
        for (int j = 0; j < 8; j++) {
            const int col = j * 8 + 2 * (lane & 3);
            *(unsigned*)&Og[((size_t)(b * SEQ + qq))     * D_MODEL + h * DEPTH + col]
                = pack2(o[j][0] * inv0, o[j][1] * inv0);
            *(unsigned*)&Og[((size_t)(b * SEQ + qq + 8)) * D_MODEL + h * DEPTH + col]
                = pack2(o[j][2] * inv1, o[j][3] * inv1);
        }
        __syncthreads();   // buffers reused from t=0 next pass
    }
}

// ---------------------------------------------------------------------------
// Launch
// ---------------------------------------------------------------------------
extern "C" void kernel_launch(void* const* d_in, const int* in_sizes, int n_in,
                              void* d_out, int out_size)
{
    const float* v       = (const float*)d_in[0];
    const float* k       = (const float*)d_in[1];
    const float* q       = (const float*)d_in[2];
    // d_in[3] = mask (causal triu) -- analytic in attn kernel
    const float* wq_w    = (const float*)d_in[4];
    const float* wq_b    = (const float*)d_in[5];
    const float* wk_w    = (const float*)d_in[6];
    const float* wk_b    = (const float*)d_in[7];
    const float* wv_w    = (const float*)d_in[8];
    const float* wv_b    = (const float*)d_in[9];
    const float* dense_w = (const float*)d_in[10];
    const float* dense_b = (const float*)d_in[11];
    float* out = (float*)d_out;

    __half *qf, *kf, *vf, *wq, *wk, *wv, *wd, *qh, *kh, *vh, *att;
    cudaGetSymbolAddress((void**)&qf,  g_qf);
    cudaGetSymbolAddress((void**)&kf,  g_kf);
    cudaGetSymbolAddress((void**)&vf,  g_vf);
    cudaGetSymbolAddress((void**)&wq,  g_wq);
    cudaGetSymbolAddress((void**)&wk,  g_wk);
    cudaGetSymbolAddress((void**)&wv,  g_wv);
    cudaGetSymbolAddress((void**)&wd,  g_wd);
    cudaGetSymbolAddress((void**)&qh,  g_qh);
    cudaGetSymbolAddress((void**)&kh,  g_kh);
    cudaGetSymbolAddress((void**)&vh,  g_vh);
    cudaGetSymbolAddress((void**)&att, g_att);

    cudaFuncSetAttribute(gemm_qkv,
                         cudaFuncAttributeMaxDynamicSharedMemorySize, GEMM_SMEM_BYTES);
    cudaFuncSetAttribute(gemm_dense,
                         cudaFuncAttributeMaxDynamicSharedMemorySize, GEMM_SMEM_BYTES);

    // 1) f32 -> f16 conversions (single launch; wq pre-scaled by QSCALE)
    cvt_all<<<dim3(M_ROWS * D_MODEL / 4 / 256, 1, 7), 256>>>(
        q, k, v, wq_w, wk_w, wv_w, dense_w,
        qf, kf, vf, wq, wk, wv, wd);

    // 2) Q/K/V projections (head-split half output)
    const dim3 pgrid(D_MODEL / 128, M_ROWS / 128, 3);   // (8, 32, 3)
    gemm_qkv<<<pgrid, 256, GEMM_SMEM_BYTES>>>(qf, kf, vf, wq, wq_b, wk, wk_b,
                                              wv, wv_b, qh, kh, vh);

    // 3) attention (half in, half out)
    const dim3 agrid(SEQ / 256, NUM_HEADS, BATCH);      // (8, 16, 2) paired tiles
    attn_h<<<agrid, ATTN_THREADS>>>(qh, kh, vh, att);

    // 4) dense (half in, f32 out)
    const dim3 dgrid(D_MODEL / 128, M_ROWS / 128);      // (8, 32)
    gemm_dense<<<dgrid, 256, GEMM_SMEM_BYTES>>>(att, wd, dense_b, out);
}

// round 17
// speedup vs baseline: 1.0881x; 1.0881x over previous
#include <cuda_runtime.h>
#include <cuda_fp16.h>
#include <cstddef>
#include <cstdint>

#define D_MODEL   1024
#define NUM_HEADS 16
#define DEPTH     64
#define BATCH     2
#define SEQ       2048
#define M_ROWS    (BATCH * SEQ)   // 4096

// Q-path scale: (1/sqrt(64)) * log2(e)  — folds softmax scaling + exp->ex2
#define QSCALE 0.18033688011112042f

// ---------------------------------------------------------------------------
// Scratch (all fp16 intermediates; f32 only for biases & final output)
// ---------------------------------------------------------------------------
__device__ __half g_qf[M_ROWS * D_MODEL];    // converted inputs
__device__ __half g_kf[M_ROWS * D_MODEL];
__device__ __half g_vf[M_ROWS * D_MODEL];
__device__ __half g_wq[D_MODEL * D_MODEL];   // converted weights (wq pre-scaled)
__device__ __half g_wk[D_MODEL * D_MODEL];
__device__ __half g_wv[D_MODEL * D_MODEL];
__device__ __half g_wd[D_MODEL * D_MODEL];
__device__ __half g_qh[BATCH * NUM_HEADS * SEQ * DEPTH];   // projections [B,H,S,64]
__device__ __half g_kh[BATCH * NUM_HEADS * SEQ * DEPTH];
__device__ __half g_vh[BATCH * NUM_HEADS * SEQ * DEPTH];
__device__ __half g_att[M_ROWS * D_MODEL];   // attention out, concat layout

// ---------------------------------------------------------------------------
// Helpers
// ---------------------------------------------------------------------------
__device__ __forceinline__ uint32_t smem_u32(const void* p) {
    uint32_t a;
    asm("{ .reg .u64 t; cvta.to.shared.u64 t, %1; cvt.u32.u64 %0, t; }" : "=r"(a) : "l"(p));
    return a;
}

__device__ __forceinline__ unsigned pack2(float a, float b) {
    __half2 h = __floats2half2_rn(a, b);   // low half = a
    return *reinterpret_cast<unsigned*>(&h);
}

__device__ __forceinline__ float ex2f(float x) {
    float y;
    asm("ex2.approx.f32 %0, %1;" : "=f"(y) : "f"(x));
    return y;
}

// paired exponential: ex2 on both halves of a packed half2
__device__ __forceinline__ unsigned h2ex2(unsigned x) {
    unsigned y;
    asm("ex2.approx.f16x2 %0, %1;" : "=r"(y) : "r"(x));
    return y;
}

__device__ __forceinline__ void mma16(float* c, const unsigned* a, const unsigned* b) {
    asm volatile(
        "mma.sync.aligned.m16n8k16.row.col.f32.f16.f16.f32 "
        "{%0,%1,%2,%3},{%4,%5,%6,%7},{%8,%9},{%0,%1,%2,%3};"
        : "+f"(c[0]), "+f"(c[1]), "+f"(c[2]), "+f"(c[3])
        : "r"(a[0]), "r"(a[1]), "r"(a[2]), "r"(a[3]), "r"(b[0]), "r"(b[1]));
}

__device__ __forceinline__ void ldm_x4(unsigned* d, uint32_t addr) {
    asm volatile("ldmatrix.sync.aligned.m8n8.x4.shared.b16 {%0,%1,%2,%3}, [%4];"
                 : "=r"(d[0]), "=r"(d[1]), "=r"(d[2]), "=r"(d[3]) : "r"(addr));
}
__device__ __forceinline__ void ldm_x4_t(unsigned* d, uint32_t addr) {
    asm volatile("ldmatrix.sync.aligned.m8n8.x4.trans.shared.b16 {%0,%1,%2,%3}, [%4];"
                 : "=r"(d[0]), "=r"(d[1]), "=r"(d[2]), "=r"(d[3]) : "r"(addr));
}

#define CP16(dst, src) \
    asm volatile("cp.async.cg.shared.global [%0], [%1], 16;" :: "r"(dst), "l"(src) : "memory")
#define CP_COMMIT() asm volatile("cp.async.commit_group;" ::: "memory")
#define CP_WAIT(n)  asm volatile("cp.async.wait_group %0;" :: "n"(n) : "memory")

// ---------------------------------------------------------------------------
// Conversion kernel (f32 -> f16): z 0..2 inputs (q,k,v), 3..6 weights.
// wq (z==3) pre-scaled by QSCALE.
// ---------------------------------------------------------------------------
__global__ void cvt_all(const float* __restrict__ q, const float* __restrict__ k,
                        const float* __restrict__ v,
                        const float* __restrict__ w0, const float* __restrict__ w1,
                        const float* __restrict__ w2, const float* __restrict__ w3,
                        __half* dq, __half* dk, __half* dv,
                        __half* d0, __half* d1, __half* d2, __half* d3)
{
    const int z = blockIdx.z;
    const int n = (z < 3) ? (M_ROWS * D_MODEL / 4) : (D_MODEL * D_MODEL / 4);
    const int i = blockIdx.x * blockDim.x + threadIdx.x;
    if (i >= n) return;
    const float* s;
    __half* d;
    float sc = 1.0f;
    switch (z) {
        case 0: s = q;  d = dq; break;
        case 1: s = k;  d = dk; break;
        case 2: s = v;  d = dv; break;
        case 3: s = w0; d = d0; sc = QSCALE; break;
        case 4: s = w1; d = d1; break;
        case 5: s = w2; d = d2; break;
        default: s = w3; d = d3; break;
    }
    const float4 f = ((const float4*)s)[i];
    uint2 u;
    u.x = pack2(f.x * sc, f.y * sc);
    u.y = pack2(f.z * sc, f.w * sc);
    ((uint2*)d)[i] = u;
}

// ---------------------------------------------------------------------------
// fp16 GEMM (exact R13 core): C = A(M,K) @ W^T(N,K) + bias*bscale.
// Block 128x128, BK=32, 256 thr, 8 warps (2m x 4n), warp tile 64x32,
// 5-stage cp.async pipeline (dynamic smem 80KB; wait_group 3).
//   GOFF(r,c) = (r>>1)*128 + ((((r&1)*4 + c) ^ ((r>>1)&7)) * 16)   [bytes]
// ---------------------------------------------------------------------------
#define GOFF(r, c) ((((r) >> 1) * 128) + ((((((r) & 1) * 4) + (c)) ^ (((r) >> 1) & 7)) * 16))
#define GEMM_NSTEPS 32   // 1024 / 32
#define GEMM_NSTAGE 5
#define GEMM_STAGE_BYTES 16384
#define GEMM_SMEM_BYTES (GEMM_NSTAGE * GEMM_STAGE_BYTES)   // 81920

__device__ __forceinline__ void gemm_h_core(
    const __half* __restrict__ A, const __half* __restrict__ W,
    const float* __restrict__ bias, void* __restrict__ Cout,
    int head_split, int m0, int n0, float bscale)
{
    extern __shared__ __align__(16) char gsm[];
    const uint32_t sb = smem_u32(gsm);

    const int tid  = threadIdx.x;
    const int lane = tid & 31;
    const int w    = tid >> 5;
    const int wm   = w >> 2;           // 0..1
    const int wn   = w & 3;            // 0..3

    float acc[4][4][4];
#pragma unroll
    for (int i = 0; i < 4; i++)
#pragma unroll
        for (int j = 0; j < 4; j++)
#pragma unroll
            for (int e = 0; e < 4; e++) acc[i][j][e] = 0.f;

    const int srow = tid & 127;
    const __half* gsrc = (tid < 128) ? (A + (size_t)(m0 + srow) * D_MODEL)
                                     : (W + (size_t)(n0 + srow) * D_MODEL);
    uint32_t sdst[4];
#pragma unroll
    for (int c = 0; c < 4; c++)
        sdst[c] = sb + ((tid < 128) ? 0 : 8192) + GOFF(srow, c);

    // prologue: stages 0..3 (4 groups in flight)
#pragma unroll
    for (int st = 0; st < 4; st++) {
#pragma unroll
        for (int c = 0; c < 4; c++)
            CP16(sdst[c] + st * GEMM_STAGE_BYTES, gsrc + st * 32 + c * 8);
        CP_COMMIT();
    }

    uint32_t a_off[4][2], b_off[2][2];
#pragma unroll
    for (int i = 0; i < 4; i++) {
        const int r = wm * 64 + i * 16 + (lane & 7) + ((lane >> 3) & 1) * 8;
#pragma unroll
        for (int kt = 0; kt < 2; kt++) {
            const int c = 2 * kt + (lane >> 4);
            a_off[i][kt] = GOFF(r, c);
        }
    }
#pragma unroll
    for (int jp = 0; jp < 2; jp++) {
        const int r = wn * 32 + (2 * jp + ((lane >> 4) & 1)) * 8 + (lane & 7);
#pragma unroll
        for (int kt = 0; kt < 2; kt++) {
            const int c = 2 * kt + ((lane >> 3) & 1);
            b_off[jp][kt] = GOFF(r, c);
        }
    }

#pragma unroll 1
    for (int s = 0; s < GEMM_NSTEPS; s++) {
        CP_WAIT(3);            // group s retired (one group committed per iter)
        __syncthreads();
        if (s + 4 < GEMM_NSTEPS) {
            const int st = (s + 4) % GEMM_NSTAGE;
#pragma unroll
            for (int c = 0; c < 4; c++)
                CP16(sdst[c] + st * GEMM_STAGE_BYTES, gsrc + (s + 4) * 32 + c * 8);
        }
        CP_COMMIT();           // always one group per iteration (may be empty)

        const uint32_t ab = sb + (s % GEMM_NSTAGE) * GEMM_STAGE_BYTES;
        const uint32_t bb = ab + 8192;
#pragma unroll
        for (int kt = 0; kt < 2; kt++) {
            unsigned bf[4][2];
#pragma unroll
            for (int jp = 0; jp < 2; jp++) {
                unsigned t4[4];
                ldm_x4(t4, bb + b_off[jp][kt]);
                bf[2 * jp][0]     = t4[0]; bf[2 * jp][1]     = t4[1];
                bf[2 * jp + 1][0] = t4[2]; bf[2 * jp + 1][1] = t4[3];
            }
#pragma unroll
            for (int i = 0; i < 4; i++) {
                unsigned af[4];
                ldm_x4(af, ab + a_off[i][kt]);
#pragma unroll
                for (int j = 0; j < 4; j++) mma16(acc[i][j], af, bf[j]);
            }
        }
    }

    // ---- epilogue ----
#pragma unroll
    for (int i = 0; i < 4; i++) {
#pragma unroll
        for (int j = 0; j < 4; j++) {
            const int m = m0 + wm * 64 + i * 16 + (lane >> 2);
            const int n = n0 + wn * 32 + j * 8 + 2 * (lane & 3);
            const float2 bb2 = *(const float2*)(bias + n);
            const float bx = bb2.x * bscale, by = bb2.y * bscale;
            const float v00 = acc[i][j][0] + bx, v01 = acc[i][j][1] + by;
            const float v10 = acc[i][j][2] + bx, v11 = acc[i][j][3] + by;
            if (head_split) {
                __half* C = (__half*)Cout;
                const int hh = n >> 6, d = n & 63;
                const int b0r = m >> 11, s0r = m & (SEQ - 1);
                const int b1r = (m + 8) >> 11, s1r = (m + 8) & (SEQ - 1);
                *(unsigned*)&C[(((size_t)b0r * NUM_HEADS + hh) * SEQ + s0r) * DEPTH + d] = pack2(v00, v01);
                *(unsigned*)&C[(((size_t)b1r * NUM_HEADS + hh) * SEQ + s1r) * DEPTH + d] = pack2(v10, v11);
            } else {
                float* C = (float*)Cout;
                float2 o0; o0.x = v00; o0.y = v01;
                float2 o1; o1.x = v10; o1.y = v11;
                *(float2*)&C[(size_t)m * D_MODEL + n] = o0;
                *(float2*)&C[(size_t)(m + 8) * D_MODEL + n] = o1;
            }
        }
    }
}

__global__ __launch_bounds__(256, 2) void gemm_qkv(
    const __half* __restrict__ qf, const __half* __restrict__ kf, const __half* __restrict__ vf,
    const __half* __restrict__ wq, const float* __restrict__ bq,
    const __half* __restrict__ wk, const float* __restrict__ bk,
    const __half* __restrict__ wv, const float* __restrict__ bv,
    __half* __restrict__ qh, __half* __restrict__ kh, __half* __restrict__ vh)
{
    const int z = blockIdx.z;
    const __half* A = (z == 0) ? qf : (z == 1) ? kf : vf;
    const __half* W = (z == 0) ? wq : (z == 1) ? wk : wv;
    const float*  B = (z == 0) ? bq : (z == 1) ? bk : bv;
    __half*       C = (z == 0) ? qh : (z == 1) ? kh : vh;
    const float bs  = (z == 0) ? QSCALE : 1.0f;
    gemm_h_core(A, W, B, C, 1, blockIdx.y * 128, blockIdx.x * 128, bs);
}

__global__ __launch_bounds__(256, 2) void gemm_dense(
    const __half* __restrict__ A, const __half* __restrict__ W,
    const float* __restrict__ bias, float* __restrict__ C)
{
    gemm_h_core(A, W, bias, C, 0, blockIdx.y * 128, blockIdx.x * 128, 1.0f);
}

// ---------------------------------------------------------------------------
// fp16 FA2 causal attention, log2-domain softmax, paired f16x2 ex2.
// NEW: 256 q/block, 8 warps x 32 q-rows (two m16 groups u=0,1); each K/V
// B-fragment ldmatrix is shared across both u -> smem traffic per flop halved.
// 64-key tiles, paired q-tiles (bx, 7-bx), double-buffered cp.async K/V.
// 1 CTA/SM (regs ~190).
// ---------------------------------------------------------------------------
#define KOFF(r, c) ((r) * 128 + (((c) ^ ((r) & 7)) * 16))
#define ATTN_THREADS 256

__global__ __launch_bounds__(ATTN_THREADS, 1) void attn_h(
    const __half* __restrict__ Qg, const __half* __restrict__ Kg,
    const __half* __restrict__ Vg, __half* __restrict__ Og)
{
    __shared__ __align__(16) char asmm[2 * 16384];   // 2 bufs x (K 8KB + V 8KB)
    const uint32_t sb = smem_u32(asmm);

    const int tid  = threadIdx.x;
    const int lane = tid & 31;
    const int w    = tid >> 5;      // 0..7, each warp owns 32 q rows
    const int b    = blockIdx.z;
    const int h    = blockIdx.y;

    const size_t hoff = ((size_t)(b * NUM_HEADS + h) * SEQ) * DEPTH;
    const __half* kb = Kg + hoff;
    const __half* vb = Vg + hoff;

    const int r0 = lane >> 2;   // 0..7
    const int c0 = lane & 3;    // 0..3

    // staging (unchanged): t<128 -> K, else V; row (t&127)>>1, chunks (t&1)*4..+3
    const int strow = (tid & 127) >> 1;
    const int stc0  = (tid & 1) * 4;
    const __half* stsrc = ((tid < 128) ? kb : vb) + (size_t)strow * DEPTH + stc0 * 8;
    uint32_t stdst[4];
#pragma unroll
    for (int i = 0; i < 4; i++)
        stdst[i] = sb + ((tid < 128) ? 0 : 8192) + KOFF(strow, stc0 + i);

    int rK[4];
#pragma unroll
    for (int jp = 0; jp < 4; jp++)
        rK[jp] = (2 * jp + ((lane >> 4) & 1)) * 8 + (lane & 7);
    const int hK  = (lane >> 3) & 1;
    const int rVl = (lane & 7) + ((lane >> 3) & 1) * 8;
    const int cVb = (lane >> 4) & 1;

#pragma unroll 1
    for (int pass = 0; pass < 2; pass++) {
        const int p  = pass ? (7 - (int)blockIdx.x) : (int)blockIdx.x;
        const int q0 = p * 256;

        // Q A-frags for both row-groups
        unsigned qa[2][4][4];
#pragma unroll
        for (int u = 0; u < 2; u++) {
            const __half* qb = Qg + hoff + (size_t)(q0 + w * 32 + u * 16) * DEPTH;
#pragma unroll
            for (int kt = 0; kt < 4; kt++) {
                qa[u][kt][0] = *(const unsigned*)(qb + (size_t)(r0)     * DEPTH + kt * 16 + 2 * c0);
                qa[u][kt][1] = *(const unsigned*)(qb + (size_t)(r0 + 8) * DEPTH + kt * 16 + 2 * c0);
                qa[u][kt][2] = *(const unsigned*)(qb + (size_t)(r0)     * DEPTH + kt * 16 + 8 + 2 * c0);
                qa[u][kt][3] = *(const unsigned*)(qb + (size_t)(r0 + 8) * DEPTH + kt * 16 + 8 + 2 * c0);
            }
        }

        float o[2][8][4];
#pragma unroll
        for (int u = 0; u < 2; u++)
#pragma unroll
            for (int j = 0; j < 8; j++)
#pragma unroll
                for (int e = 0; e < 4; e++) o[u][j][e] = 0.f;
        float m0r[2] = {-1e30f, -1e30f}, m1r[2] = {-1e30f, -1e30f};
        float l0r[2] = {0.f, 0.f},       l1r[2] = {0.f, 0.f};

        const int ntile = 4 * p + 4;
        const int qhiW  = q0 + w * 32 + 31;

#pragma unroll
        for (int i = 0; i < 4; i++) CP16(stdst[i], stsrc + i * 8);
        CP_COMMIT();

#pragma unroll 1
        for (int t = 0; t < ntile; t++) {
            CP_WAIT(0);
            __syncthreads();
            if (t + 1 < ntile) {
                const uint32_t bo = ((t + 1) & 1) * 16384;
                const __half* src = stsrc + (size_t)(t + 1) * 64 * DEPTH;
#pragma unroll
                for (int i = 0; i < 4; i++) CP16(stdst[i] + bo, src + i * 8);
                CP_COMMIT();
            }
            if (t * 64 > qhiW) continue;   // fully masked for this warp

            const uint32_t kbuf = sb + (t & 1) * 16384;
            const uint32_t vbuf = kbuf + 8192;

            // ---- S = Q @ K^T, K-frags shared across u ----
            float s[2][8][4];
#pragma unroll
            for (int u = 0; u < 2; u++)
#pragma unroll
                for (int j = 0; j < 8; j++)
#pragma unroll
                    for (int e = 0; e < 4; e++) s[u][j][e] = 0.f;
#pragma unroll
            for (int kt = 0; kt < 4; kt++) {
#pragma unroll
                for (int jp = 0; jp < 4; jp++) {
                    unsigned t4[4];
                    ldm_x4(t4, kbuf + rK[jp] * 128 + (((2 * kt + hK) ^ (rK[jp] & 7)) << 4));
                    unsigned bf0[2] = {t4[0], t4[1]};
                    unsigned bf1[2] = {t4[2], t4[3]};
#pragma unroll
                    for (int u = 0; u < 2; u++) {
                        mma16(s[u][2 * jp],     qa[u][kt], bf0);
                        mma16(s[u][2 * jp + 1], qa[u][kt], bf1);
                    }
                }
            }

            // ---- causal mask + online softmax per row-group ----
            unsigned p01[2][8], p23[2][8];
#pragma unroll
            for (int u = 0; u < 2; u++) {
                const int qlow = q0 + w * 32 + u * 16;
                const bool diag = (t * 64 + 63 > qlow);
                const int qrow = qlow + r0;
                float mx0 = -1e30f, mx1 = -1e30f;
#pragma unroll
                for (int j = 0; j < 8; j++) {
                    if (diag) {
#pragma unroll
                        for (int e = 0; e < 4; e++) {
                            const int key = t * 64 + j * 8 + 2 * (lane & 3) + (e & 1);
                            const int qq  = qrow + ((e >> 1) << 3);
                            if (key > qq) s[u][j][e] = -1e30f;
                        }
                    }
                    mx0 = fmaxf(mx0, fmaxf(s[u][j][0], s[u][j][1]));
                    mx1 = fmaxf(mx1, fmaxf(s[u][j][2], s[u][j][3]));
                }
                mx0 = fmaxf(mx0, __shfl_xor_sync(0xffffffffu, mx0, 1));
                mx0 = fmaxf(mx0, __shfl_xor_sync(0xffffffffu, mx0, 2));
                mx1 = fmaxf(mx1, __shfl_xor_sync(0xffffffffu, mx1, 1));
                mx1 = fmaxf(mx1, __shfl_xor_sync(0xffffffffu, mx1, 2));

                const float mn0 = fmaxf(m0r[u], mx0);
                const float mn1 = fmaxf(m1r[u], mx1);
                const float al0 = ex2f(m0r[u] - mn0);
                const float al1 = ex2f(m1r[u] - mn1);

                __half2 a01 = __floats2half2_rn(0.f, 0.f);
                __half2 a23 = a01;
#pragma unroll
                for (int j = 0; j < 8; j++) {
                    p01[u][j] = h2ex2(pack2(s[u][j][0] - mn0, s[u][j][1] - mn0));
                    p23[u][j] = h2ex2(pack2(s[u][j][2] - mn1, s[u][j][3] - mn1));
                    a01 = __hadd2(a01, *reinterpret_cast<__half2*>(&p01[u][j]));
                    a23 = __hadd2(a23, *reinterpret_cast<__half2*>(&p23[u][j]));
                }
                float ls0 = __low2float(a01) + __high2float(a01);
                float ls1 = __low2float(a23) + __high2float(a23);
                ls0 += __shfl_xor_sync(0xffffffffu, ls0, 1);
                ls0 += __shfl_xor_sync(0xffffffffu, ls0, 2);
                ls1 += __shfl_xor_sync(0xffffffffu, ls1, 1);
                ls1 += __shfl_xor_sync(0xffffffffu, ls1, 2);

                l0r[u] = l0r[u] * al0 + ls0;
                l1r[u] = l1r[u] * al1 + ls1;
                m0r[u] = mn0; m1r[u] = mn1;

#pragma unroll
                for (int j = 0; j < 8; j++) {
                    o[u][j][0] *= al0; o[u][j][1] *= al0;
                    o[u][j][2] *= al1; o[u][j][3] *= al1;
                }
            }

            // ---- O += P @ V, V-frags shared across u ----
#pragma unroll
            for (int kt = 0; kt < 4; kt++) {
                const int rV = kt * 16 + rVl;
#pragma unroll
                for (int jp = 0; jp < 4; jp++) {
                    unsigned t4[4];
                    ldm_x4_t(t4, vbuf + rV * 128 + (((2 * jp + cVb) ^ (rV & 7)) << 4));
                    unsigned bf0[2] = {t4[0], t4[1]};
                    unsigned bf1[2] = {t4[2], t4[3]};
#pragma unroll
                    for (int u = 0; u < 2; u++) {
                        unsigned af[4];
                        af[0] = p01[u][2 * kt];
                        af[1] = p23[u][2 * kt];
                        af[2] = p01[u][2 * kt + 1];
                        af[3] = p23[u][2 * kt + 1];
                        mma16(o[u][2 * jp],     af, bf0);
                        mma16(o[u][2 * jp + 1], af, bf1);
                    }
                }
            }
        }

        // ---- epilogue ----
#pragma unroll
        for (int u = 0; u < 2; u++) {
            const float inv0 = 1.f / l0r[u];
            const float inv1 = 1.f / l1r[u];
            const int qq = q0 + w * 32 + u * 16 + r0;
#pragma unroll
            for (int j = 0; j < 8; j++) {
                const int col = j * 8 + 2 * (lane & 3);
                *(unsigned*)&Og[((size_t)(b * SEQ + qq))     * D_MODEL + h * DEPTH + col]
                    = pack2(o[u][j][0] * inv0, o[u][j][1] * inv0);
                *(unsigned*)&Og[((size_t)(b * SEQ + qq + 8)) * D_MODEL + h * DEPTH + col]
                    = pack2(o[u][j][2] * inv1, o[u][j][3] * inv1);
            }
        }
        __syncthreads();   // buffers reused from t=0 next pass
    }
}

// ---------------------------------------------------------------------------
// Launch
// ---------------------------------------------------------------------------
extern "C" void kernel_launch(void* const* d_in, const int* in_sizes, int n_in,
                              void* d_out, int out_size)
{
    const float* v       = (const float*)d_in[0];
    const float* k       = (const float*)d_in[1];
    const float* q       = (const float*)d_in[2];
    // d_in[3] = mask (causal triu) -- analytic in attn kernel
    const float* wq_w    = (const float*)d_in[4];
    const float* wq_b    = (const float*)d_in[5];
    const float* wk_w    = (const float*)d_in[6];
    const float* wk_b    = (const float*)d_in[7];
    const float* wv_w    = (const float*)d_in[8];
    const float* wv_b    = (const float*)d_in[9];
    const float* dense_w = (const float*)d_in[10];
    const float* dense_b = (const float*)d_in[11];
    float* out = (float*)d_out;

    __half *qf, *kf, *vf, *wq, *wk, *wv, *wd, *qh, *kh, *vh, *att;
    cudaGetSymbolAddress((void**)&qf,  g_qf);
    cudaGetSymbolAddress((void**)&kf,  g_kf);
    cudaGetSymbolAddress((void**)&vf,  g_vf);
    cudaGetSymbolAddress((void**)&wq,  g_wq);
    cudaGetSymbolAddress((void**)&wk,  g_wk);
    cudaGetSymbolAddress((void**)&wv,  g_wv);
    cudaGetSymbolAddress((void**)&wd,  g_wd);
    cudaGetSymbolAddress((void**)&qh,  g_qh);
    cudaGetSymbolAddress((void**)&kh,  g_kh);
    cudaGetSymbolAddress((void**)&vh,  g_vh);
    cudaGetSymbolAddress((void**)&att, g_att);

    cudaFuncSetAttribute(gemm_qkv,
                         cudaFuncAttributeMaxDynamicSharedMemorySize, GEMM_SMEM_BYTES);
    cudaFuncSetAttribute(gemm_dense,
                         cudaFuncAttributeMaxDynamicSharedMemorySize, GEMM_SMEM_BYTES);

    // 1) f32 -> f16 conversions (single launch; wq pre-scaled by QSCALE)
    cvt_all<<<dim3(M_ROWS * D_MODEL / 4 / 256, 1, 7), 256>>>(
        q, k, v, wq_w, wk_w, wv_w, dense_w,
        qf, kf, vf, wq, wk, wv, wd);

    // 2) Q/K/V projections (head-split half output)
    const dim3 pgrid(D_MODEL / 128, M_ROWS / 128, 3);   // (8, 32, 3)
    gemm_qkv<<<pgrid, 256, GEMM_SMEM_BYTES>>>(qf, kf, vf, wq, wq_b, wk, wk_b,
                                              wv, wv_b, qh, kh, vh);

    // 3) attention (half in, half out), 256 q/block
    const dim3 agrid(SEQ / 512, NUM_HEADS, BATCH);      // (4, 16, 2) paired tiles
    attn_h<<<agrid, ATTN_THREADS>>>(qh, kh, vh, att);

    // 4) dense (half in, f32 out)
    const dim3 dgrid(D_MODEL / 128, M_ROWS / 128);      // (8, 32)
    gemm_dense<<<dgrid, 256, GEMM_SMEM_BYTES>>>(att, wd, dense_b, out);
}